// round 5
// baseline (speedup 1.0000x reference)
#include <cuda_runtime.h>

#define NLAYERS 7
#define EPS_F 1e-5f

// Shapes (fixed by setup_inputs): bsz=8, C=8, QL=KL=128, A=8, cross_range=2
// pw / out: [64, 1024, 1024] f32;  conv_w: [7,8,8,1,3]; conv_b: [7,8]; prelu_a: [7]
//
// One CTA per (b, q). Per output row (4KB), the nonzero band is ONE contiguous
// 160B segment (block-cols i-2..i+2, self block zero). The zero left/right
// remainders are written by TMA bulk stores (cp.async.bulk G<-S) from a 4KB
// SMEM zero buffer, issued BEFORE the conv so DRAM streams during compute.
// Band values are STG'd at the end (disjoint addresses -> no WAW hazard).

__device__ __forceinline__ void stcs4(float* p, float4 v) {
    asm volatile("st.global.cs.v4.f32 [%0], {%1,%2,%3,%4};"
                 :: "l"(p), "f"(v.x), "f"(v.y), "f"(v.z), "f"(v.w) : "memory");
}
__device__ __forceinline__ void bulk_store(float* gptr, unsigned saddr, unsigned bytes) {
    asm volatile("cp.async.bulk.global.shared::cta.bulk_group [%0], [%1], %2;"
                 :: "l"(gptr), "r"(saddr), "r"(bytes) : "memory");
}

__global__ __launch_bounds__(256, 5)
void sag_merged(const float* __restrict__ pw,
                const float* __restrict__ conv_w,
                const float* __restrict__ conv_b,
                const float* __restrict__ prelu_a,
                float* __restrict__ out)
{
    __shared__ float4 sW4[NLAYERS][8][8];            // [l][ci][co] = (k0,k1,k2,_)
    __shared__ float  sB [NLAYERS][8];
    __shared__ float  sA [NLAYERS];
    __shared__ __align__(16) float sZero[1024];      // 4KB of zeros (TMA source)
    __shared__ __align__(16) float sD0[32 * 68];     // ping  [slab]*68 + [ci]*8 + w
    __shared__ __align__(16) float sD1[32 * 68];     // pong
    __shared__ __align__(16) float sRes[4][8][8][8]; // x, later we  [pp][hh][co][w]
    __shared__ float  sPS[4][8][8];                  // partial row sums
    __shared__ float  sInv[8][8];                    // 1/(rowsum+eps) [hh][co]

    const int tid = threadIdx.x;
    const int b = blockIdx.x >> 7;            // batch
    const int i = blockIdx.x & 127;           // query index

    // ---- conv params -> SMEM; zero buffer ----
    for (int t = tid; t < NLAYERS * 64; t += 256) {
        const int l = t >> 6, rem = t & 63, wco = rem >> 3, wci = rem & 7;
        const float* src = conv_w + ((l * 8 + wco) * 8 + wci) * 3;
        sW4[l][wci][wco] = make_float4(src[0], src[1], src[2], 0.f);
    }
    if (tid < NLAYERS * 8) (&sB[0][0])[tid] = conv_b[tid];
    if (tid < NLAYERS)     sA[tid] = prelu_a[tid];
    ((float4*)sZero)[tid] = make_float4(0.f, 0.f, 0.f, 0.f);

    // compute roles: slab = pp*8 + hh, co = channel
    const int slab = tid >> 3;
    const int co   = tid & 7;
    const int pp   = slab >> 3;
    const int hh   = slab & 7;
    const int doff = (pp < 2) ? (pp - 2) : (pp - 1);  // {-2,-1,1,2}
    const int j    = i + doff;
    const bool pvalid = (j >= 0) && (j < 128);

    // ---- issue x loads early ----
    float4 v0 = make_float4(0.f, 0.f, 0.f, 0.f), v1 = v0;
    if (pvalid) {
        const float* src = pw +
            ((size_t)((b * 8 + co) * 1024 + (i * 8 + hh)) * 1024 + (size_t)j * 8);
        v0 = *(const float4*)src;
        v1 = *(const float4*)(src + 4);
    }

    const size_t base = ((size_t)(b * 8) * 1024 + (size_t)i * 8) * 1024;
    const int lo = (i - 2 > 0)   ? i - 2 : 0;     // first band block-col
    const int hi = (i + 2 < 127) ? i + 2 : 127;   // last band block-col

    __syncthreads();   // zero buffer + params visible

    // ---- TMA zero streaming: threads 0..63 own one output row each ----
    if (tid < 64) {
        asm volatile("fence.proxy.async.shared::cta;" ::: "memory");
        const int rc = tid >> 3, rh = tid & 7;
        float* row = out + base + (size_t)rc * (1024 * 1024) + (size_t)rh * 1024;
        const unsigned zsrc = (unsigned)__cvta_generic_to_shared(sZero);
        const unsigned leftB  = (unsigned)lo * 32u;          // bytes before band
        const unsigned rightB = (unsigned)(127 - hi) * 32u;  // bytes after band
        if (leftB)  bulk_store(row, zsrc, leftB);
        if (rightB) bulk_store(row + (hi + 1) * 8, zsrc, rightB);
        asm volatile("cp.async.bulk.commit_group;" ::: "memory");
    }

    // ---- seed ping buffer + stash x in sRes ----
    {
        float* row = sD0 + slab * 68 + co * 8;
        *(float4*)row       = v0;
        *(float4*)(row + 4) = v1;
        *(float4*)&sRes[pp][hh][co][0] = v0;
        *(float4*)&sRes[pp][hh][co][4] = v1;
    }
    __syncthreads();

    // ---- 7-layer residual conv stack ----
    float* cur = sD0;
    float* nxt = sD1;
    #pragma unroll 1
    for (int l = 0; l < NLAYERS; l++) {
        const float bias = sB[l][co];
        float acc[8];
        #pragma unroll
        for (int w = 0; w < 8; w++) acc[w] = bias;

        #pragma unroll
        for (int ci = 0; ci < 8; ci++) {
            const float4 wv = sW4[l][ci][co];
            const float* inr = cur + slab * 68 + ci * 8;
            const float4 ra = *(const float4*)inr;
            const float4 rb = *(const float4*)(inr + 4);
            acc[0] += wv.y * ra.x + wv.z * ra.y;
            acc[1] += wv.x * ra.x + wv.y * ra.y + wv.z * ra.z;
            acc[2] += wv.x * ra.y + wv.y * ra.z + wv.z * ra.w;
            acc[3] += wv.x * ra.z + wv.y * ra.w + wv.z * rb.x;
            acc[4] += wv.x * ra.w + wv.y * rb.x + wv.z * rb.y;
            acc[5] += wv.x * rb.x + wv.y * rb.y + wv.z * rb.z;
            acc[6] += wv.x * rb.y + wv.y * rb.z + wv.z * rb.w;
            acc[7] += wv.x * rb.z + wv.y * rb.w;
        }

        const float pa = sA[l];
        const float* selfr = cur + slab * 68 + co * 8;
        const float4 s0 = *(const float4*)selfr;
        const float4 s1 = *(const float4*)(selfr + 4);
        float4 o0, o1;
        o0.x = ((acc[0] >= 0.f) ? acc[0] : pa * acc[0]) + s0.x;
        o0.y = ((acc[1] >= 0.f) ? acc[1] : pa * acc[1]) + s0.y;
        o0.z = ((acc[2] >= 0.f) ? acc[2] : pa * acc[2]) + s0.z;
        o0.w = ((acc[3] >= 0.f) ? acc[3] : pa * acc[3]) + s0.w;
        o1.x = ((acc[4] >= 0.f) ? acc[4] : pa * acc[4]) + s1.x;
        o1.y = ((acc[5] >= 0.f) ? acc[5] : pa * acc[5]) + s1.y;
        o1.z = ((acc[6] >= 0.f) ? acc[6] : pa * acc[6]) + s1.z;
        o1.w = ((acc[7] >= 0.f) ? acc[7] : pa * acc[7]) + s1.w;
        float* outr = nxt + slab * 68 + co * 8;
        *(float4*)outr       = o0;
        *(float4*)(outr + 4) = o1;
        __syncthreads();
        float* tmp = cur; cur = nxt; nxt = tmp;
    }

    // ---- we = expm1(relu(x - sigmoid(conv)) * (1-eye)) ----
    {
        const float* cr = cur + slab * 68 + co * 8;
        const float4 c0 = *(const float4*)cr;
        const float4 c1 = *(const float4*)(cr + 4);
        const float4 x0 = *(const float4*)&sRes[pp][hh][co][0];
        const float4 x1 = *(const float4*)&sRes[pp][hh][co][4];
        float cv[8] = {c0.x, c0.y, c0.z, c0.w, c1.x, c1.y, c1.z, c1.w};
        float xv[8] = {x0.x, x0.y, x0.z, x0.w, x1.x, x1.y, x1.z, x1.w};
        float we[8];
        float partial = 0.f;
        #pragma unroll
        for (int w = 0; w < 8; w++) {
            const float sg = 1.f / (1.f + __expf(-cv[w]));
            float sp = fmaxf(xv[w] - sg, 0.f);
            if (hh == w) sp = 0.f;              // self mask
            float v = expm1f(sp);
            if (!pvalid) v = 0.f;
            we[w] = v;
            partial += v;
        }
        *(float4*)&sRes[pp][hh][co][0] = make_float4(we[0], we[1], we[2], we[3]);
        *(float4*)&sRes[pp][hh][co][4] = make_float4(we[4], we[5], we[6], we[7]);
        sPS[pp][hh][co] = partial;
    }
    __syncthreads();

    if (tid < 64) {
        const int th = tid >> 3, tc = tid & 7;
        const float s = sPS[0][th][tc] + sPS[1][th][tc] + sPS[2][th][tc] + sPS[3][th][tc];
        sInv[th][tc] = 1.f / (s + EPS_F);
    }
    __syncthreads();

    // ---- band stores: float4-column = tid, block-col = tid>>1 ----
    {
        const int kcol = tid >> 1;
        if (kcol >= lo && kcol <= hi) {
            const int d = kcol - i;
            int pi = -1;
            if      (d == -2) pi = 0;
            else if (d == -1) pi = 1;
            else if (d ==  1) pi = 2;
            else if (d ==  2) pi = 3;
            const int w0 = (tid & 1) * 4;
            float* p0 = out + base + (size_t)tid * 4;
            #pragma unroll 1
            for (int rc = 0; rc < 8; rc++) {
                float* pr = p0 + (size_t)rc * (1024 * 1024);
                #pragma unroll
                for (int rh = 0; rh < 8; rh++) {
                    float4 v = make_float4(0.f, 0.f, 0.f, 0.f);
                    if (pi >= 0) {
                        const float4 r = *(const float4*)&sRes[pi][rh][rc][w0];
                        const float inv = sInv[rh][rc];
                        v = make_float4(r.x * inv, r.y * inv, r.z * inv, r.w * inv);
                    }
                    stcs4(pr + rh * 1024, v);
                }
            }
        }
    }

    // ---- drain bulk stores before exit ----
    if (tid < 64)
        asm volatile("cp.async.bulk.wait_group 0;" ::: "memory");
}

extern "C" void kernel_launch(void* const* d_in, const int* in_sizes, int n_in,
                              void* d_out, int out_size) {
    const float* pw = (const float*)d_in[0];
    const float* cw = (const float*)d_in[1];
    const float* cb = (const float*)d_in[2];
    const float* pa = (const float*)d_in[3];
    sag_merged<<<1024, 256>>>(pw, cw, cb, pa, (float*)d_out);
}

// round 6
// speedup vs baseline: 1.4922x; 1.4922x over previous
#include <cuda_runtime.h>

#define NLAYERS 7
#define EPS_F 1e-5f

// Shapes (fixed by setup_inputs): bsz=8, C=8, QL=KL=128, A=8, cross_range=2
// pw / out: [64, 1024, 1024] f32;  conv_w: [7,8,8,1,3]; conv_b: [7,8]; prelu_a: [7]
//
// One CTA per (b, q). The 256KB output region per CTA is 98% zeros
// (expm1(0)=0, 0/(sum+eps)=0). Zero stores are INTERLEAVED with the 7-layer
// conv stack (one 8-store slice per layer) so DRAM write bandwidth is fed
// continuously instead of in phase bursts. Band values are STG'd at the end.

__device__ __forceinline__ void stcs4(float* p, float4 v) {
    asm volatile("st.global.cs.v4.f32 [%0], {%1,%2,%3,%4};"
                 :: "l"(p), "f"(v.x), "f"(v.y), "f"(v.z), "f"(v.w) : "memory");
}

// one slice = this thread's float4-column across the 8 rows of channel rc
__device__ __forceinline__ void zero_slice(float* colbase, int rc) {
    const float4 z = make_float4(0.f, 0.f, 0.f, 0.f);
    float* pr = colbase + (size_t)rc * (1024 * 1024);
    #pragma unroll
    for (int rh = 0; rh < 8; rh++)
        stcs4(pr + rh * 1024, z);
}

__global__ __launch_bounds__(256, 5)
void sag_merged(const float* __restrict__ pw,
                const float* __restrict__ conv_w,
                const float* __restrict__ conv_b,
                const float* __restrict__ prelu_a,
                float* __restrict__ out)
{
    __shared__ float4 sW4[NLAYERS][8][8];            // [l][ci][co] = (k0,k1,k2,_)
    __shared__ float  sB [NLAYERS][8];
    __shared__ float  sA [NLAYERS];
    __shared__ __align__(16) float sD0[32 * 68];     // ping  [slab]*68 + [ci]*8 + w
    __shared__ __align__(16) float sD1[32 * 68];     // pong
    __shared__ __align__(16) float sRes[4][8][8][8]; // x, later we  [pp][hh][co][w]
    __shared__ float  sPS[4][8][8];                  // partial row sums
    __shared__ float  sInv[8][8];                    // 1/(rowsum+eps) [hh][co]

    const int tid = threadIdx.x;
    const int b = blockIdx.x >> 7;            // batch
    const int i = blockIdx.x & 127;           // query index

    // ---- conv params -> SMEM (weights repacked [l][ci][co] as float4) ----
    for (int t = tid; t < NLAYERS * 64; t += 256) {
        const int l = t >> 6, rem = t & 63, wco = rem >> 3, wci = rem & 7;
        const float* src = conv_w + ((l * 8 + wco) * 8 + wci) * 3;
        sW4[l][wci][wco] = make_float4(src[0], src[1], src[2], 0.f);
    }
    if (tid < NLAYERS * 8) (&sB[0][0])[tid] = conv_b[tid];
    if (tid < NLAYERS)     sA[tid] = prelu_a[tid];

    // compute roles: slab = pp*8 + hh, co = channel
    const int slab = tid >> 3;
    const int co   = tid & 7;
    const int pp   = slab >> 3;
    const int hh   = slab & 7;
    const int doff = (pp < 2) ? (pp - 2) : (pp - 1);  // {-2,-1,1,2}
    const int j    = i + doff;
    const bool pvalid = (j >= 0) && (j < 128);

    // ---- issue x loads early ----
    float4 v0 = make_float4(0.f, 0.f, 0.f, 0.f), v1 = v0;
    if (pvalid) {
        const float* src = pw +
            ((size_t)((b * 8 + co) * 1024 + (i * 8 + hh)) * 1024 + (size_t)j * 8);
        v0 = *(const float4*)src;
        v1 = *(const float4*)(src + 4);
    }

    // store roles: float4-column = tid, block column k = tid>>1
    const int kcol = tid >> 1;
    const int d    = kcol - i;
    int pi = -1;
    if      (d == -2) pi = 0;
    else if (d == -1) pi = 1;
    else if (d ==  1) pi = 2;
    else if (d ==  2) pi = 3;
    const size_t base = ((size_t)(b * 8) * 1024 + (size_t)i * 8) * 1024;
    float* colbase = out + base + (size_t)tid * 4;
    const bool zcol = (pi < 0);               // this column is all zeros

    // ---- slice 0 of zero stores (channel row 0) ----
    if (zcol) zero_slice(colbase, 0);

    // ---- seed ping buffer + stash x in sRes ----
    {
        float* row = sD0 + slab * 68 + co * 8;
        *(float4*)row       = v0;
        *(float4*)(row + 4) = v1;
        *(float4*)&sRes[pp][hh][co][0] = v0;
        *(float4*)&sRes[pp][hh][co][4] = v1;
    }
    __syncthreads();

    // ---- 7-layer residual conv stack, zero-store slice l+1 inside layer l ----
    float* cur = sD0;
    float* nxt = sD1;
    #pragma unroll 1
    for (int l = 0; l < NLAYERS; l++) {
        const float bias = sB[l][co];
        float acc[8];
        #pragma unroll
        for (int w = 0; w < 8; w++) acc[w] = bias;

        #pragma unroll
        for (int ci = 0; ci < 8; ci++) {
            const float4 wv = sW4[l][ci][co];
            const float* inr = cur + slab * 68 + ci * 8;
            const float4 ra = *(const float4*)inr;
            const float4 rb = *(const float4*)(inr + 4);
            acc[0] += wv.y * ra.x + wv.z * ra.y;
            acc[1] += wv.x * ra.x + wv.y * ra.y + wv.z * ra.z;
            acc[2] += wv.x * ra.y + wv.y * ra.z + wv.z * ra.w;
            acc[3] += wv.x * ra.z + wv.y * ra.w + wv.z * rb.x;
            acc[4] += wv.x * ra.w + wv.y * rb.x + wv.z * rb.y;
            acc[5] += wv.x * rb.x + wv.y * rb.y + wv.z * rb.z;
            acc[6] += wv.x * rb.y + wv.y * rb.z + wv.z * rb.w;
            acc[7] += wv.x * rb.z + wv.y * rb.w;
        }

        // interleaved zero-store slice (independent of conv data; overlaps)
        if (zcol) zero_slice(colbase, l + 1);

        const float pa = sA[l];
        const float* selfr = cur + slab * 68 + co * 8;
        const float4 s0 = *(const float4*)selfr;
        const float4 s1 = *(const float4*)(selfr + 4);
        float4 o0, o1;
        o0.x = ((acc[0] >= 0.f) ? acc[0] : pa * acc[0]) + s0.x;
        o0.y = ((acc[1] >= 0.f) ? acc[1] : pa * acc[1]) + s0.y;
        o0.z = ((acc[2] >= 0.f) ? acc[2] : pa * acc[2]) + s0.z;
        o0.w = ((acc[3] >= 0.f) ? acc[3] : pa * acc[3]) + s0.w;
        o1.x = ((acc[4] >= 0.f) ? acc[4] : pa * acc[4]) + s1.x;
        o1.y = ((acc[5] >= 0.f) ? acc[5] : pa * acc[5]) + s1.y;
        o1.z = ((acc[6] >= 0.f) ? acc[6] : pa * acc[6]) + s1.z;
        o1.w = ((acc[7] >= 0.f) ? acc[7] : pa * acc[7]) + s1.w;
        float* outr = nxt + slab * 68 + co * 8;
        *(float4*)outr       = o0;
        *(float4*)(outr + 4) = o1;
        __syncthreads();
        float* tmp = cur; cur = nxt; nxt = tmp;
    }

    // ---- we = expm1(relu(x - sigmoid(conv)) * (1-eye)) ----
    {
        const float* cr = cur + slab * 68 + co * 8;
        const float4 c0 = *(const float4*)cr;
        const float4 c1 = *(const float4*)(cr + 4);
        const float4 x0 = *(const float4*)&sRes[pp][hh][co][0];
        const float4 x1 = *(const float4*)&sRes[pp][hh][co][4];
        float cv[8] = {c0.x, c0.y, c0.z, c0.w, c1.x, c1.y, c1.z, c1.w};
        float xv[8] = {x0.x, x0.y, x0.z, x0.w, x1.x, x1.y, x1.z, x1.w};
        float we[8];
        float partial = 0.f;
        #pragma unroll
        for (int w = 0; w < 8; w++) {
            const float sg = 1.f / (1.f + __expf(-cv[w]));
            float sp = fmaxf(xv[w] - sg, 0.f);
            if (hh == w) sp = 0.f;              // self mask
            float v = expm1f(sp);
            if (!pvalid) v = 0.f;
            we[w] = v;
            partial += v;
        }
        *(float4*)&sRes[pp][hh][co][0] = make_float4(we[0], we[1], we[2], we[3]);
        *(float4*)&sRes[pp][hh][co][4] = make_float4(we[4], we[5], we[6], we[7]);
        sPS[pp][hh][co] = partial;
    }
    __syncthreads();

    if (tid < 64) {
        const int th = tid >> 3, tc = tid & 7;
        const float s = sPS[0][th][tc] + sPS[1][th][tc] + sPS[2][th][tc] + sPS[3][th][tc];
        sInv[th][tc] = 1.f / (s + EPS_F);
    }
    __syncthreads();

    // ---- band stores: the 8 band-column threads write their column ----
    if (pi >= 0) {
        const int w0 = (tid & 1) * 4;
        #pragma unroll 1
        for (int rc = 0; rc < 8; rc++) {
            float* pr = colbase + (size_t)rc * (1024 * 1024);
            #pragma unroll
            for (int rh = 0; rh < 8; rh++) {
                const float4 r = *(const float4*)&sRes[pi][rh][rc][w0];
                const float inv = sInv[rh][rc];
                stcs4(pr + rh * 1024,
                      make_float4(r.x * inv, r.y * inv, r.z * inv, r.w * inv));
            }
        }
    }
}

extern "C" void kernel_launch(void* const* d_in, const int* in_sizes, int n_in,
                              void* d_out, int out_size) {
    const float* pw = (const float*)d_in[0];
    const float* cw = (const float*)d_in[1];
    const float* cb = (const float*)d_in[2];
    const float* pa = (const float*)d_in[3];
    sag_merged<<<1024, 256>>>(pw, cw, cb, pa, (float*)d_out);
}